// round 16
// baseline (speedup 1.0000x reference)
#include <cuda_runtime.h>
#include <cuda_bf16.h>
#include <cstdint>

// ---------------- problem constants ----------------
#define TT   128
#define BB   64
#define HH   512
#define VV   10000

#define KTILES 48            // logical K' = 1536 in 32-elem tiles
#define MTILES 64            // 8192 / 128
#define NTILES 40            // 40*256 = 10240
#define TM     128
#define TN     256
#define QTOTAL (MTILES * NTILES)   // 2560

#define REC_CTAS  64
#define ALL_CTAS  148

#define OUT_STATE_OFF 81920000u
#define OUT_CELL_OFF  81952768u

// swizzles:
//  swzH: 2048B rows (rec W tiles)
//  swzQ: 1024B rows (rec h blocks)
//  swzG: 64B rows   (gemm blocks)
__device__ __forceinline__ uint32_t swzH(uint32_t off) { return off ^ (((off >> 11) & 7u) << 4); }
__device__ __forceinline__ uint32_t swzQ(uint32_t off) { return off ^ (((off >> 10) & 7u) << 4); }
__device__ __forceinline__ uint32_t swzG(uint32_t off) { return off ^ ((off >> 3) & 0x30u); }

// ---------------- device scratch ----------------
// g_A2 slot t (131072B) = block0 (64 rows x 1024B, k<256: hi512|lo512, swzQ)
//                       + block1 (same for k>=256)
__device__ __align__(16) char  g_A2[(size_t)(TT + 1) * 131072];
__device__ __align__(16) char  g_GA[(size_t)MTILES * 32 * 8192];     // gemm A blocks, swzG
__device__ __align__(16) char  g_GB[(size_t)NTILES * 32 * 16384];    // gemm B blocks, swzG
__device__ __align__(16) char  g_WB[(size_t)64 * 65536];             // rec W regions, swzH
__device__ __align__(16) float g_XQ[(size_t)TT * BB * 2048];         // x-preact (bias folded)
__device__ unsigned g_cnt  = 0;   // rec step barrier counter (monotonic; reset at start)
__device__ unsigned g_cnt0 = 0;   // start barrier counter (148)
__device__ unsigned g_gen  = 0;   // monotonic progress counter
__device__ unsigned g_tq   = 0;   // tile work queue head (reset at start barrier)

// fast approx activations (ex2/rcp approx: rel err ~1e-6; on the serial chain)
__device__ __forceinline__ float fast_ex2(float x) {
    float r; asm("ex2.approx.f32 %0, %1;" : "=f"(r) : "f"(x)); return r;
}
__device__ __forceinline__ float fast_rcp(float x) {
    float r; asm("rcp.approx.f32 %0, %1;" : "=f"(r) : "f"(x)); return r;
}
__device__ __forceinline__ float fast_sigmoid(float x) {
    return fast_rcp(1.0f + fast_ex2(-1.4426950408889634f * x));
}
__device__ __forceinline__ float fast_tanh(float x) {
    float s = fast_rcp(1.0f + fast_ex2(-2.8853900817779268f * x));
    return fmaf(2.0f, s, -1.0f);
}

__device__ __forceinline__ uint32_t smem_u32(const void* p) {
    uint32_t a;
    asm("{ .reg .u64 t; cvta.to.shared.u64 t, %1; cvt.u32.u64 %0, t; }" : "=r"(a) : "l"(p));
    return a;
}
__device__ __forceinline__ void cp_async16(uint32_t dst, const void* src) {
    asm volatile("cp.async.cg.shared.global [%0], [%1], 16;" :: "r"(dst), "l"(src));
}
__device__ __forceinline__ void bulk_g2s(uint32_t dst, const void* src, uint32_t bytes, uint32_t mbar) {
    asm volatile("cp.async.bulk.shared::cluster.global.mbarrier::complete_tx::bytes "
                 "[%0], [%1], %2, [%3];"
                 :: "r"(dst), "l"(src), "r"(bytes), "r"(mbar) : "memory");
}
#define MBARRIER_INIT(addr, cnt) \
    asm volatile("mbarrier.init.shared.b64 [%0], %1;" :: "r"(addr), "r"(cnt) : "memory")
#define MBARRIER_EXPECT_TX(addr, tx) \
    asm volatile("mbarrier.arrive.expect_tx.shared.b64 _, [%0], %1;" :: "r"(addr), "r"(tx) : "memory")
#define MBARRIER_ARRIVE(addr) \
    asm volatile("mbarrier.arrive.shared.b64 _, [%0];" :: "r"(addr) : "memory")
#define MBARRIER_WAIT_PARITY(mbar, par) do {                                    \
    uint32_t _m = (mbar); uint32_t _p = (par); uint32_t _d;                     \
    asm volatile("{\n\t.reg .pred p;\n\t"                                       \
        "mbarrier.try_wait.parity.acquire.cta.shared::cta.b64 p, [%1], %2;\n\t" \
        "selp.b32 %0, 1, 0, p;\n\t}" : "=r"(_d) : "r"(_m), "r"(_p) : "memory"); \
    if (!_d) {                                                                  \
        asm volatile("{\n\t.reg .pred P1;\n\t"                                  \
        "WL_%=:\n\t"                                                            \
        "mbarrier.try_wait.parity.acquire.cta.shared::cta.b64 P1, [%0], %1, 0x989680;\n\t" \
        "@P1 bra.uni WD_%=;\n\t"                                                \
        "bra.uni WL_%=;\n\t"                                                    \
        "WD_%=:\n\t}" :: "r"(_m), "r"(_p) : "memory");                          \
    } } while (0)

__device__ __forceinline__ void ldsm_x4(uint32_t* r, uint32_t addr) {
    asm volatile("ldmatrix.sync.aligned.m8n8.x4.shared.b16 {%0,%1,%2,%3}, [%4];"
                 : "=r"(r[0]), "=r"(r[1]), "=r"(r[2]), "=r"(r[3]) : "r"(addr));
}
__device__ __forceinline__ void mma16816(float* c, const uint32_t* a, uint32_t b0, uint32_t b1) {
    asm volatile("mma.sync.aligned.m16n8k16.row.col.f32.bf16.bf16.f32 "
                 "{%0,%1,%2,%3}, {%4,%5,%6,%7}, {%8,%9}, {%0,%1,%2,%3};"
                 : "+f"(c[0]), "+f"(c[1]), "+f"(c[2]), "+f"(c[3])
                 : "r"(a[0]), "r"(a[1]), "r"(a[2]), "r"(a[3]), "r"(b0), "r"(b1));
}

// ---------------- merged prep: weights + x-preacts + state0 -------------------
// blk < 1024:              W_h* -> g_WB (swzH)
// blk in [1024, 2304):     W_hq -> g_GB blocks (swzG)
// blk in [2304, 18688):    x-preacts (bias folded) -> g_XQ
// blk in [18688, 18704):   state0 -> g_A2 slot 0 (swzQ)
__global__ void __launch_bounds__(256)
prep_all(const float* __restrict__ Whq,
         const float* __restrict__ Wi, const float* __restrict__ Wf,
         const float* __restrict__ Wo, const float* __restrict__ Wc,
         const int* __restrict__ x, const float* __restrict__ state0,
         const float* __restrict__ Wxi, const float* __restrict__ Wxf,
         const float* __restrict__ Wxo, const float* __restrict__ Wxc,
         const float* __restrict__ bi,  const float* __restrict__ bf_,
         const float* __restrict__ bo,  const float* __restrict__ bc) {
    __shared__ float tile[32 * 257];
    const int blk = blockIdx.x;
    const int tid = threadIdx.x;
    if (blk < 1024) {
        const int kt = blk & 15, jt = (blk >> 4) & 15, g = blk >> 8;
        const float* W = (g == 0) ? Wi : (g == 1) ? Wf : (g == 2) ? Wo : Wc;
        for (int i = tid; i < 1024; i += 256) {
            int kk = i >> 5, jj = i & 31;
            tile[kk * 33 + jj] = W[(kt * 32 + kk) * HH + jt * 32 + jj];
        }
        __syncthreads();
        for (int i = tid; i < 1024; i += 256) {
            int jj = i >> 5, kk = i & 31;
            float w = tile[kk * 33 + jj];
            int j   = jt * 32 + jj;
            int cta = j >> 3;
            int row = g * 8 + (j & 7);
            uint32_t offh = (uint32_t)(row * 2048 + (kt * 32 + kk) * 2);
            __nv_bfloat16 hi = __float2bfloat16(w);
            __nv_bfloat16 lo = __float2bfloat16(w - __bfloat162float(hi));
            char* base = g_WB + (size_t)cta * 65536;
            *reinterpret_cast<__nv_bfloat16*>(base + swzH(offh))        = hi;
            *reinterpret_cast<__nv_bfloat16*>(base + swzH(offh + 1024)) = lo;
        }
    } else if (blk < 2304) {
        const int b  = blk - 1024;
        const int kc = b & 31;
        const int nt = b >> 5;
        const bool lo = (kc >= 16);
        const int ksrc = (lo ? (kc - 16) : kc) * 32;
        for (int i = tid; i < 32 * 256; i += 256) {
            int kk = i >> 8, nn = i & 255;
            int n = nt * 256 + nn;
            tile[kk * 257 + nn] = (n < VV) ? Whq[(ksrc + kk) * VV + n] : 0.0f;
        }
        __syncthreads();
        char* blkbase = g_GB + (size_t)(nt * 32 + kc) * 16384;
        for (int c = tid; c < 1024; c += 256) {
            int row = c >> 2, ch = c & 3;
            __nv_bfloat16 v[8];
            #pragma unroll
            for (int i = 0; i < 8; i++) {
                float w = tile[(ch * 8 + i) * 257 + row];
                __nv_bfloat16 hi = __float2bfloat16(w);
                v[i] = lo ? __float2bfloat16(w - __bfloat162float(hi)) : hi;
            }
            uint32_t off = (uint32_t)(row * 64 + ch * 16);
            *reinterpret_cast<int4*>(blkbase + swzG(off)) = *reinterpret_cast<int4*>(v);
        }
    } else if (blk < 18688) {
        int idx = (blk - 2304) * 256 + tid;
        int f4  = idx & 7;
        int b   = (idx >> 3) & 63;
        int cta = (idx >> 9) & 63;
        int t   = idx >> 15;
        int col0 = f4 * 4;
        int g  = col0 >> 3;
        int u0 = col0 & 7;
        const float* W  = (g == 0) ? Wxi : (g == 1) ? Wxf : (g == 2) ? Wxo : Wxc;
        const float* bb = (g == 0) ? bi  : (g == 1) ? bf_ : (g == 2) ? bo  : bc;
        int tok = x[b * TT + t];
        float4 w  = *reinterpret_cast<const float4*>(&W[(size_t)tok * HH + cta * 8 + u0]);
        float4 bv = *reinterpret_cast<const float4*>(&bb[cta * 8 + u0]);
        float4 o = {w.x + bv.x, w.y + bv.y, w.z + bv.z, w.w + bv.w};
        *reinterpret_cast<float4*>(&g_XQ[(size_t)idx * 4]) = o;
    } else {
        int idx = (blk - 18688) * 256 + tid;
        if (idx >= BB * 64) return;
        int m = idx >> 6, kp = (idx & 63) * 8;
        const float* src = state0 + (size_t)m * HH + kp;
        float4 f0 = *reinterpret_cast<const float4*>(src);
        float4 f1 = *reinterpret_cast<const float4*>(src + 4);
        float fv[8] = {f0.x, f0.y, f0.z, f0.w, f1.x, f1.y, f1.z, f1.w};
        __nv_bfloat16 hv[8], lv[8];
        #pragma unroll
        for (int i = 0; i < 8; i++) {
            __nv_bfloat16 hi = __float2bfloat16(fv[i]);
            hv[i] = hi;
            lv[i] = __float2bfloat16(fv[i] - __bfloat162float(hi));
        }
        char* base = g_A2 + (size_t)(kp >> 8) * 65536;
        uint32_t off = (uint32_t)(m * 1024 + (kp & 255) * 2);
        *reinterpret_cast<int4*>(base + swzQ(off))        = *reinterpret_cast<int4*>(hv);
        *reinterpret_cast<int4*>(base + swzQ(off + 512))  = *reinterpret_cast<int4*>(lv);
    }
}

// ---------------- fused persistent kernel ------------------------------------
#define SM_H   0                // 131072 (h: block0 64KB + block1 64KB)
#define SM_W   131072           // 65536 (rec W, swzH 2048B rows)
#define SM_XQ  196608           // 8192
#define SM_P   204800           // 8192
#define SM_C   212992           // 2048
#define SM_TOT 215040

#define GSTAGES 4
#define GA_B 8192
#define GB_B 16384
#define GST_B (GA_B + GB_B)     // 24576; 4 stages = 98304 < SM_TOT

// one 128x256 output tile; data bars (count 1) + free bars (count 256).
__device__ __forceinline__ void gemm_tile(
    uint32_t sbase, uint32_t bar0, uint32_t fbar0, unsigned* ps, unsigned* fs,
    int mt, int nt, int tid, int wid, int lid,
    const float* __restrict__ bq, float* __restrict__ out)
{
    const int m0 = mt * TM, n0 = nt * TN;
    const int wm = (wid >> 2) * 64, wn = (wid & 3) * 64;
    const int lr = lid & 15,  lc = (lid >> 4) * 16;

    auto akc = [](int kt) { return (kt < 32) ? kt : kt - 32; };
    auto bkc = [](int kt) { return (kt < 16) ? kt : kt - 16; };

    float acc[4][8][4];
    #pragma unroll
    for (int i = 0; i < 4; i++)
        #pragma unroll
        for (int jn = 0; jn < 8; jn++)
            #pragma unroll
            for (int q = 0; q < 4; q++) acc[i][jn][q] = 0.0f;

    if (tid == 0) {
        #pragma unroll
        for (int s = 0; s < GSTAGES; s++) {
            uint32_t b = bar0 + s * 8;
            MBARRIER_EXPECT_TX(b, (uint32_t)GST_B);
            bulk_g2s(sbase + s * GST_B,         g_GA + (size_t)(mt * 32 + akc(s)) * GA_B, GA_B, b);
            bulk_g2s(sbase + s * GST_B + GA_B,  g_GB + (size_t)(nt * 32 + bkc(s)) * GB_B, GB_B, b);
        }
    }

    for (int t = 0; t < KTILES; t++) {
        const int s = t % GSTAGES;
        MBARRIER_WAIT_PARITY(bar0 + s * 8, ps[s] & 1u);
        ps[s]++;

        const uint32_t Ab = sbase + s * GST_B;
        const uint32_t Bb = Ab + GA_B;
        uint32_t af[2][4][4], bf[2][4][4];
        #pragma unroll
        for (int ks2 = 0; ks2 < 2; ks2++) {
            #pragma unroll
            for (int i = 0; i < 4; i++)
                ldsm_x4(af[ks2][i], Ab + swzG((uint32_t)((wm + i * 16 + lr) * 64 + ks2 * 32 + lc)));
            #pragma unroll
            for (int jn = 0; jn < 4; jn++)
                ldsm_x4(bf[ks2][jn], Bb + swzG((uint32_t)((wn + jn * 16 + lr) * 64 + ks2 * 32 + lc)));
        }
        MBARRIER_ARRIVE(fbar0 + s * 8);
        unsigned fp = fs[s]++;
        if (t + GSTAGES < KTILES && tid == 0) {
            MBARRIER_WAIT_PARITY(fbar0 + s * 8, fp & 1u);
            int kt = t + GSTAGES;
            uint32_t b = bar0 + s * 8;
            MBARRIER_EXPECT_TX(b, (uint32_t)GST_B);
            bulk_g2s(sbase + s * GST_B,        g_GA + (size_t)(mt * 32 + akc(kt)) * GA_B, GA_B, b);
            bulk_g2s(sbase + s * GST_B + GA_B, g_GB + (size_t)(nt * 32 + bkc(kt)) * GB_B, GB_B, b);
        }
        #pragma unroll
        for (int ks2 = 0; ks2 < 2; ks2++)
            #pragma unroll
            for (int i = 0; i < 4; i++)
                #pragma unroll
                for (int jn = 0; jn < 4; jn++) {
                    mma16816(acc[i][2 * jn],     af[ks2][i], bf[ks2][jn][0], bf[ks2][jn][2]);
                    mma16816(acc[i][2 * jn + 1], af[ks2][i], bf[ks2][jn][1], bf[ks2][jn][3]);
                }
    }

    const int qr = lid >> 2;
    const int qc = (lid & 3) * 2;
    #pragma unroll
    for (int i = 0; i < 4; i++) {
        int mrow = m0 + wm + i * 16 + qr;
        #pragma unroll
        for (int jn = 0; jn < 8; jn++) {
            int n = n0 + wn + jn * 8 + qc;
            if (n < VV) {
                float bx = bq[n], by = bq[n + 1 < VV ? n + 1 : n];
                float2 v0 = {acc[i][jn][0] + bx, acc[i][jn][1] + by};
                float2 v1 = {acc[i][jn][2] + bx, acc[i][jn][3] + by};
                *reinterpret_cast<float2*>(out + (size_t)mrow * VV + n) = v0;
                *reinterpret_cast<float2*>(out + (size_t)(mrow + 8) * VV + n) = v1;
            }
        }
    }
}

__device__ __forceinline__ void gemm_drain(
    uint32_t sbase, uint32_t bar0, uint32_t fbar0, unsigned* ps, unsigned* fs,
    unsigned base, int tid, int wid, int lid, unsigned* s_q,
    const float* __restrict__ bq, float* __restrict__ out)
{
    for (;;) {
        if (tid == 0) *s_q = atomicAdd(&g_tq, 1u);
        __syncthreads();
        unsigned q = *s_q;
        __syncthreads();
        if (q >= QTOTAL) break;
        int mt = (int)(q / NTILES), nt = (int)(q % NTILES);
        if (tid == 0) {
            while ((*(volatile unsigned*)&g_gen) - base < (unsigned)(2 * mt + 3))
                __nanosleep(100);
            __threadfence();
        }
        __syncthreads();
        gemm_tile(sbase, bar0, fbar0, ps, fs, mt, nt, tid, wid, lid, bq, out);
    }
}

__global__ void __launch_bounds__(256, 1)
lstm_fused(const float* __restrict__ cell0, const float* __restrict__ bq,
           float* __restrict__ out) {
    extern __shared__ __align__(128) char sm[];
    __shared__ __align__(8) uint64_t s_hbar[2];
    __shared__ __align__(8) uint64_t s_gbar[GSTAGES];
    __shared__ __align__(8) uint64_t s_gfree[GSTAGES];
    __shared__ unsigned s_base;
    __shared__ unsigned s_q;
    const uint32_t hbase = smem_u32(sm);
    const uint32_t hbar0 = smem_u32(&s_hbar[0]);
    const uint32_t gbar0 = smem_u32(&s_gbar[0]);
    const uint32_t gfree0 = smem_u32(&s_gfree[0]);

    const int tid = threadIdx.x;
    const int wid = tid >> 5;
    const int lid = tid & 31;
    const int cta = blockIdx.x;

    if (tid == 0) {
        MBARRIER_INIT(hbar0, 1);
        MBARRIER_INIT(hbar0 + 8, 1);
        for (int s = 0; s < GSTAGES; s++) {
            MBARRIER_INIT(gbar0 + s * 8, 1);
            MBARRIER_INIT(gfree0 + s * 8, 256);
        }
    }
    __syncthreads();

    // ---- start barrier: capture g_gen base; CTA0 resets queue + step ctr ----
    if (tid == 0) {
        unsigned b = *(volatile unsigned*)&g_gen;
        s_base = b;
        if (cta == 0) {
            atomicExch(&g_tq, 0u);
            atomicExch(&g_cnt, 0u);
        }
        __threadfence();
        unsigned arr = atomicAdd(&g_cnt0, 1u);
        if (arr == ALL_CTAS - 1) {
            atomicExch(&g_cnt0, 0u);
            __threadfence();
            atomicAdd(&g_gen, 1u);
        }
        while ((*(volatile unsigned*)&g_gen) - b < 1u) __nanosleep(40);
    }
    __syncthreads();
    const unsigned base = s_base;
    unsigned ps[GSTAGES] = {0, 0, 0, 0};
    unsigned fs[GSTAGES] = {0, 0, 0, 0};

    if (cta < REC_CTAS) {
        // ================= recurrence (CTAs 0..63) =================
        const uint32_t wbase = hbase + SM_W;
        const uint32_t xqb   = hbase + SM_XQ;
        float* pbuf  = reinterpret_cast<float*>(sm + SM_P);
        float* cellb = reinterpret_cast<float*>(sm + SM_C);
        float* sxq   = reinterpret_cast<float*>(sm + SM_XQ);

        const int j0  = cta * 8;
        const int mg  = wid >> 1;
        const int ng  = wid & 1;
        const int lr  = lid & 15;
        const int lc  = (lid >> 4) * 16;
        const int eb  = tid >> 2;
        const int u0  = (tid & 3) * 2;
        const int j   = j0 + u0;

        {
            const char* src = g_WB + (size_t)cta * 65536;
            for (int c = tid; c < 4096; c += 256)
                cp_async16(wbase + c * 16, src + (size_t)c * 16);
            asm volatile("cp.async.commit_group;" ::: "memory");
        }
        for (int i = tid; i < 512; i += 256)
            cellb[i] = cell0[(size_t)(i >> 3) * HH + j0 + (i & 7)];
        asm volatile("cp.async.wait_group 0;" ::: "memory");
        __syncthreads();

        const uint32_t rowA = (uint32_t)((mg * 16 + lr) * 1024);
        const uint32_t rowW = (uint32_t)((ng * 16 + lr) * 2048);

        char* const a2wr = g_A2 + (size_t)(j >> 8) * 65536;
        const uint32_t offw_hi = (uint32_t)(eb * 1024 + (j & 255) * 2);

        for (int t = 0; t < TT; t++) {
            if (tid == 0) {
                const char* slot = g_A2 + (size_t)t * 131072;
                MBARRIER_EXPECT_TX(hbar0, 65536u);
                bulk_g2s(hbase, slot, 65536u, hbar0);
                MBARRIER_EXPECT_TX(hbar0 + 8, 65536u + 8192u);
                bulk_g2s(hbase + 65536, slot + 65536, 65536u, hbar0 + 8);
                bulk_g2s(xqb, (const char*)g_XQ + ((size_t)(t * 64 + cta)) * 8192, 8192u, hbar0 + 8);
            }

            float acc0[4] = {0.f, 0.f, 0.f, 0.f};
            float acc1[4] = {0.f, 0.f, 0.f, 0.f};

            // half 0 (k < 256)
            MBARRIER_WAIT_PARITY(hbar0, (uint32_t)(t & 1));
            #pragma unroll 4
            for (int kt = 0; kt < 16; kt++) {
                uint32_t ahi[4], alo[4], bhi[4], blo[4];
                uint32_t ca = rowA + kt * 32 + lc;
                uint32_t cw = rowW + kt * 32 + lc;
                ldsm_x4(ahi, hbase + swzQ(ca));
                ldsm_x4(alo, hbase + swzQ(ca + 512));
                ldsm_x4(bhi, wbase + swzH(cw));
                ldsm_x4(blo, wbase + swzH(cw + 1024));
                mma16816(acc0, ahi, bhi[0], bhi[2]);
                mma16816(acc1, ahi, bhi[1], bhi[3]);
                mma16816(acc0, alo, bhi[0], bhi[2]);
                mma16816(acc1, alo, bhi[1], bhi[3]);
                mma16816(acc0, ahi, blo[0], blo[2]);
                mma16816(acc1, ahi, blo[1], blo[3]);
            }
            // half 1 (k >= 256)
            MBARRIER_WAIT_PARITY(hbar0 + 8, (uint32_t)(t & 1));
            #pragma unroll 4
            for (int kt = 16; kt < 32; kt++) {
                uint32_t ahi[4], alo[4], bhi[4], blo[4];
                uint32_t ca = rowA + (kt - 16) * 32 + lc;
                uint32_t cw = rowW + kt * 32 + lc;
                ldsm_x4(ahi, hbase + 65536 + swzQ(ca));
                ldsm_x4(alo, hbase + 65536 + swzQ(ca + 512));
                ldsm_x4(bhi, wbase + swzH(cw));
                ldsm_x4(blo, wbase + swzH(cw + 1024));
                mma16816(acc0, ahi, bhi[0], bhi[2]);
                mma16816(acc1, ahi, bhi[1], bhi[3]);
                mma16816(acc0, alo, bhi[0], bhi[2]);
                mma16816(acc1, alo, bhi[1], bhi[3]);
                mma16816(acc0, ahi, blo[0], blo[2]);
                mma16816(acc1, ahi, blo[1], blo[3]);
            }

            {
                const int qr = lid >> 2;
                const int qc = (lid & 3) * 2;
                int row = mg * 16 + qr;
                int col = ng * 16 + qc;
                pbuf[row * 32 + col]           = acc0[0];
                pbuf[row * 32 + col + 1]       = acc0[1];
                pbuf[(row + 8) * 32 + col]     = acc0[2];
                pbuf[(row + 8) * 32 + col + 1] = acc0[3];
                pbuf[row * 32 + col + 8]       = acc1[0];
                pbuf[row * 32 + col + 9]       = acc1[1];
                pbuf[(row + 8) * 32 + col + 8] = acc1[2];
                pbuf[(row + 8) * 32 + col + 9] = acc1[3];
            }
            __syncthreads();

            {
                const float* pr = pbuf + eb * 32;
                const float* xr = sxq  + eb * 32;
                float i0 = fast_sigmoid(pr[u0]          + xr[u0]);
                float i1 = fast_sigmoid(pr[u0 + 1]      + xr[u0 + 1]);
                float f0 = fast_sigmoid(pr[8 + u0]      + xr[8 + u0]);
                float f1 = fast_sigmoid(pr[8 + u0 + 1]  + xr[8 + u0 + 1]);
                float o0 = fast_sigmoid(pr[16 + u0]     + xr[16 + u0]);
                float o1 = fast_sigmoid(pr[16 + u0 + 1] + xr[16 + u0 + 1]);
                float g0 = fast_tanh   (pr[24 + u0]     + xr[24 + u0]);
                float g1 = fast_tanh   (pr[24 + u0 + 1] + xr[24 + u0 + 1]);

                float c0 = cellb[eb * 8 + u0];
                float c1 = cellb[eb * 8 + u0 + 1];
                float cn0 = fmaf(f0, c0, i0 * g0);
                float cn1 = fmaf(f1, c1, i1 * g1);
                cellb[eb * 8 + u0]     = cn0;
                cellb[eb * 8 + u0 + 1] = cn1;
                float hn0 = o0 * fast_tanh(cn0);
                float hn1 = o1 * fast_tanh(cn1);

                __nv_bfloat16 h0 = __float2bfloat16(hn0);
                __nv_bfloat16 h1 = __float2bfloat16(hn1);
                __nv_bfloat16 l0 = __float2bfloat16(hn0 - __bfloat162float(h0));
                __nv_bfloat16 l1 = __float2bfloat16(hn1 - __bfloat162float(h1));
                uint32_t hib = (uint32_t)__bfloat16_as_ushort(h0) |
                               ((uint32_t)__bfloat16_as_ushort(h1) << 16);
                uint32_t lob = (uint32_t)__bfloat16_as_ushort(l0) |
                               ((uint32_t)__bfloat16_as_ushort(l1) << 16);
                char* dst = a2wr + (size_t)(t + 1) * 131072;
                *reinterpret_cast<uint32_t*>(dst + swzQ(offw_hi))        = hib;
                *reinterpret_cast<uint32_t*>(dst + swzQ(offw_hi + 512))  = lob;
                int mt  = t >> 1;
                int row = ((t & 1) << 6) | eb;
                int kcH = j >> 5;
                uint32_t offg = (uint32_t)(row * 64 + ((j & 31) * 2));
                char* ga  = g_GA + (size_t)(mt * 32 + kcH) * GA_B;
                char* gal = g_GA + (size_t)(mt * 32 + 16 + kcH) * GA_B;
                *reinterpret_cast<uint32_t*>(ga  + swzG(offg)) = hib;
                *reinterpret_cast<uint32_t*>(gal + swzG(offg)) = lob;
                if (t == TT - 1) {
                    float2 hv = {hn0, hn1};
                    *reinterpret_cast<float2*>(out + OUT_STATE_OFF + (size_t)eb * HH + j) = hv;
                }
            }
            __syncthreads();
            // rec step barrier: monotonic counter
            if (tid == 0) {
                __threadfence();
                unsigned arr = atomicAdd(&g_cnt, 1u);
                if (arr == (unsigned)((t + 1) * REC_CTAS - 1)) {
                    __threadfence();
                    atomicAdd(&g_gen, 1u);
                } else if (t < TT - 1) {
                    while ((*(volatile unsigned*)&g_gen) - base < (unsigned)(t + 2))
                        __nanosleep(40);
                }
                __threadfence();
            }
            __syncthreads();
        }

        for (int i = tid; i < 512; i += 256)
            out[OUT_CELL_OFF + (size_t)(i >> 3) * HH + j0 + (i & 7)] = cellb[i];
        __syncthreads();

        gemm_drain(hbase, gbar0, gfree0, ps, fs, base, tid, wid, lid, &s_q, bq, out);
    } else {
        gemm_drain(hbase, gbar0, gfree0, ps, fs, base, tid, wid, lid, &s_q, bq, out);
    }
}

// ---------------- launch ----------------
extern "C" void kernel_launch(void* const* d_in, const int* in_sizes, int n_in,
                              void* d_out, int out_size) {
    const int*   x     = (const int*)  d_in[0];
    const float* state = (const float*)d_in[1];
    const float* cell  = (const float*)d_in[2];
    const float* W_xi  = (const float*)d_in[3];
    const float* W_hi  = (const float*)d_in[4];
    const float* b_i   = (const float*)d_in[5];
    const float* W_xf  = (const float*)d_in[6];
    const float* W_hf  = (const float*)d_in[7];
    const float* b_f   = (const float*)d_in[8];
    const float* W_xo  = (const float*)d_in[9];
    const float* W_ho  = (const float*)d_in[10];
    const float* b_o   = (const float*)d_in[11];
    const float* W_xc  = (const float*)d_in[12];
    const float* W_hc  = (const float*)d_in[13];
    const float* b_c   = (const float*)d_in[14];
    const float* W_hq  = (const float*)d_in[15];
    const float* b_q   = (const float*)d_in[16];
    float* out = (float*)d_out;

    cudaFuncSetAttribute(lstm_fused, cudaFuncAttributeMaxDynamicSharedMemorySize, SM_TOT);

    prep_all<<<18704, 256>>>(W_hq, W_hi, W_hf, W_ho, W_hc,
                             x, state, W_xi, W_xf, W_xo, W_xc,
                             b_i, b_f, b_o, b_c);
    lstm_fused<<<ALL_CTAS, 256, SM_TOT>>>(cell, b_q, out);
}

// round 17
// speedup vs baseline: 1.0206x; 1.0206x over previous
#include <cuda_runtime.h>
#include <cuda_bf16.h>
#include <cstdint>

// ---------------- problem constants ----------------
#define TT   128
#define BB   64
#define HH   512
#define VV   10000

#define KTILES 48            // logical K' = 1536 in 32-elem tiles
#define MTILES 64            // 8192 / 128
#define NTILES 40            // 40*256 = 10240
#define TM     128
#define TN     256
#define QTOTAL (MTILES * NTILES)   // 2560

#define REC_CTAS  64
#define ALL_CTAS  148

#define OUT_STATE_OFF 81920000u
#define OUT_CELL_OFF  81952768u

// swizzles:
//  swzH: 2048B rows (rec W tiles)
//  swzQ: 1024B rows (rec h blocks)
//  swzG: 64B rows   (gemm blocks)
__device__ __forceinline__ uint32_t swzH(uint32_t off) { return off ^ (((off >> 11) & 7u) << 4); }
__device__ __forceinline__ uint32_t swzQ(uint32_t off) { return off ^ (((off >> 10) & 7u) << 4); }
__device__ __forceinline__ uint32_t swzG(uint32_t off) { return off ^ ((off >> 3) & 0x30u); }

// ---------------- device scratch ----------------
// g_A2 slot t (131072B) = block0 (64 rows x 1024B, k<256: hi512|lo512, swzQ)
//                       + block1 (same for k>=256)
__device__ __align__(16) char  g_A2[(size_t)(TT + 1) * 131072];
__device__ __align__(16) char  g_GA[(size_t)MTILES * 32 * 8192];     // gemm A blocks, swzG
__device__ __align__(16) char  g_GB[(size_t)NTILES * 32 * 16384];    // gemm B blocks, swzG
__device__ __align__(16) char  g_WB[(size_t)64 * 65536];             // rec W regions, swzH
__device__ __align__(16) float g_XQ[(size_t)TT * BB * 2048];         // x-preact (bias folded)
__device__ unsigned g_cnt  = 0;   // rec step barrier counter (monotonic; reset at start)
__device__ unsigned g_cnt0 = 0;   // start barrier counter (148)
__device__ unsigned g_gen  = 0;   // monotonic progress counter
__device__ unsigned g_tq   = 0;   // tile work queue head (reset at start barrier)

__device__ __forceinline__ float sigmoidf_(float x) { return 1.0f / (1.0f + expf(-x)); }

__device__ __forceinline__ uint32_t smem_u32(const void* p) {
    uint32_t a;
    asm("{ .reg .u64 t; cvta.to.shared.u64 t, %1; cvt.u32.u64 %0, t; }" : "=r"(a) : "l"(p));
    return a;
}
__device__ __forceinline__ void cp_async16(uint32_t dst, const void* src) {
    asm volatile("cp.async.cg.shared.global [%0], [%1], 16;" :: "r"(dst), "l"(src));
}
__device__ __forceinline__ void bulk_g2s(uint32_t dst, const void* src, uint32_t bytes, uint32_t mbar) {
    asm volatile("cp.async.bulk.shared::cluster.global.mbarrier::complete_tx::bytes "
                 "[%0], [%1], %2, [%3];"
                 :: "r"(dst), "l"(src), "r"(bytes), "r"(mbar) : "memory");
}
#define MBARRIER_INIT(addr, cnt) \
    asm volatile("mbarrier.init.shared.b64 [%0], %1;" :: "r"(addr), "r"(cnt) : "memory")
#define MBARRIER_EXPECT_TX(addr, tx) \
    asm volatile("mbarrier.arrive.expect_tx.shared.b64 _, [%0], %1;" :: "r"(addr), "r"(tx) : "memory")
#define MBARRIER_ARRIVE(addr) \
    asm volatile("mbarrier.arrive.shared.b64 _, [%0];" :: "r"(addr) : "memory")
#define BAR_SYNC_PAIR(id) \
    asm volatile("bar.sync %0, 64;" :: "r"(id) : "memory")
#define MBARRIER_WAIT_PARITY(mbar, par) do {                                    \
    uint32_t _m = (mbar); uint32_t _p = (par); uint32_t _d;                     \
    asm volatile("{\n\t.reg .pred p;\n\t"                                       \
        "mbarrier.try_wait.parity.acquire.cta.shared::cta.b64 p, [%1], %2;\n\t" \
        "selp.b32 %0, 1, 0, p;\n\t}" : "=r"(_d) : "r"(_m), "r"(_p) : "memory"); \
    if (!_d) {                                                                  \
        asm volatile("{\n\t.reg .pred P1;\n\t"                                  \
        "WL_%=:\n\t"                                                            \
        "mbarrier.try_wait.parity.acquire.cta.shared::cta.b64 P1, [%0], %1, 0x989680;\n\t" \
        "@P1 bra.uni WD_%=;\n\t"                                                \
        "bra.uni WL_%=;\n\t"                                                    \
        "WD_%=:\n\t}" :: "r"(_m), "r"(_p) : "memory");                          \
    } } while (0)

__device__ __forceinline__ void ldsm_x4(uint32_t* r, uint32_t addr) {
    asm volatile("ldmatrix.sync.aligned.m8n8.x4.shared.b16 {%0,%1,%2,%3}, [%4];"
                 : "=r"(r[0]), "=r"(r[1]), "=r"(r[2]), "=r"(r[3]) : "r"(addr));
}
__device__ __forceinline__ void mma16816(float* c, const uint32_t* a, uint32_t b0, uint32_t b1) {
    asm volatile("mma.sync.aligned.m16n8k16.row.col.f32.bf16.bf16.f32 "
                 "{%0,%1,%2,%3}, {%4,%5,%6,%7}, {%8,%9}, {%0,%1,%2,%3};"
                 : "+f"(c[0]), "+f"(c[1]), "+f"(c[2]), "+f"(c[3])
                 : "r"(a[0]), "r"(a[1]), "r"(a[2]), "r"(a[3]), "r"(b0), "r"(b1));
}

// ---------------- prep1: W_h* -> g_WB (swzH) and W_hq -> g_GB blocks (swzG) ---
__global__ void __launch_bounds__(256)
prep1(const float* __restrict__ Whq,
      const float* __restrict__ Wi, const float* __restrict__ Wf,
      const float* __restrict__ Wo, const float* __restrict__ Wc) {
    __shared__ float tile[32 * 257];
    const int blk = blockIdx.x;
    const int tid = threadIdx.x;
    if (blk < 1024) {
        const int kt = blk & 15, jt = (blk >> 4) & 15, g = blk >> 8;
        const float* W = (g == 0) ? Wi : (g == 1) ? Wf : (g == 2) ? Wo : Wc;
        for (int i = tid; i < 1024; i += 256) {
            int kk = i >> 5, jj = i & 31;
            tile[kk * 33 + jj] = W[(kt * 32 + kk) * HH + jt * 32 + jj];
        }
        __syncthreads();
        for (int i = tid; i < 1024; i += 256) {
            int jj = i >> 5, kk = i & 31;
            float w = tile[kk * 33 + jj];
            int j   = jt * 32 + jj;
            int cta = j >> 3;
            int row = g * 8 + (j & 7);
            uint32_t offh = (uint32_t)(row * 2048 + (kt * 32 + kk) * 2);
            __nv_bfloat16 hi = __float2bfloat16(w);
            __nv_bfloat16 lo = __float2bfloat16(w - __bfloat162float(hi));
            char* base = g_WB + (size_t)cta * 65536;
            *reinterpret_cast<__nv_bfloat16*>(base + swzH(offh))        = hi;
            *reinterpret_cast<__nv_bfloat16*>(base + swzH(offh + 1024)) = lo;
        }
    } else {
        const int b  = blk - 1024;
        const int kc = b & 31;
        const int nt = b >> 5;
        const bool lo = (kc >= 16);
        const int ksrc = (lo ? (kc - 16) : kc) * 32;
        for (int i = tid; i < 32 * 256; i += 256) {
            int kk = i >> 8, nn = i & 255;
            int n = nt * 256 + nn;
            tile[kk * 257 + nn] = (n < VV) ? Whq[(ksrc + kk) * VV + n] : 0.0f;
        }
        __syncthreads();
        char* blkbase = g_GB + (size_t)(nt * 32 + kc) * 16384;
        for (int c = tid; c < 1024; c += 256) {
            int row = c >> 2, ch = c & 3;
            __nv_bfloat16 v[8];
            #pragma unroll
            for (int i = 0; i < 8; i++) {
                float w = tile[(ch * 8 + i) * 257 + row];
                __nv_bfloat16 hi = __float2bfloat16(w);
                v[i] = lo ? __float2bfloat16(w - __bfloat162float(hi)) : hi;
            }
            uint32_t off = (uint32_t)(row * 64 + ch * 16);
            *reinterpret_cast<int4*>(blkbase + swzG(off)) = *reinterpret_cast<int4*>(v);
        }
    }
}

// ---------------- prep2: x-preacts (bias folded) + state0 -> slot 0 ----------
__global__ void __launch_bounds__(256)
prep2(const int* __restrict__ x, const float* __restrict__ state0,
      const float* __restrict__ Wxi, const float* __restrict__ Wxf,
      const float* __restrict__ Wxo, const float* __restrict__ Wxc,
      const float* __restrict__ bi,  const float* __restrict__ bf_,
      const float* __restrict__ bo,  const float* __restrict__ bc) {
    const int blk = blockIdx.x;
    const int tid = threadIdx.x;
    if (blk < 16384) {
        int idx = blk * 256 + tid;
        int f4  = idx & 7;
        int b   = (idx >> 3) & 63;
        int cta = (idx >> 9) & 63;
        int t   = idx >> 15;
        int col0 = f4 * 4;
        int g  = col0 >> 3;
        int u0 = col0 & 7;
        const float* W  = (g == 0) ? Wxi : (g == 1) ? Wxf : (g == 2) ? Wxo : Wxc;
        const float* bb = (g == 0) ? bi  : (g == 1) ? bf_ : (g == 2) ? bo  : bc;
        int tok = x[b * TT + t];
        float4 w  = *reinterpret_cast<const float4*>(&W[(size_t)tok * HH + cta * 8 + u0]);
        float4 bv = *reinterpret_cast<const float4*>(&bb[cta * 8 + u0]);
        float4 o = {w.x + bv.x, w.y + bv.y, w.z + bv.z, w.w + bv.w};
        *reinterpret_cast<float4*>(&g_XQ[(size_t)idx * 4]) = o;
    } else {
        int idx = (blk - 16384) * 256 + tid;
        if (idx >= BB * 64) return;
        int m = idx >> 6, kp = (idx & 63) * 8;
        const float* src = state0 + (size_t)m * HH + kp;
        float4 f0 = *reinterpret_cast<const float4*>(src);
        float4 f1 = *reinterpret_cast<const float4*>(src + 4);
        float fv[8] = {f0.x, f0.y, f0.z, f0.w, f1.x, f1.y, f1.z, f1.w};
        __nv_bfloat16 hv[8], lv[8];
        #pragma unroll
        for (int i = 0; i < 8; i++) {
            __nv_bfloat16 hi = __float2bfloat16(fv[i]);
            hv[i] = hi;
            lv[i] = __float2bfloat16(fv[i] - __bfloat162float(hi));
        }
        char* base = g_A2 + (size_t)(kp >> 8) * 65536;
        uint32_t off = (uint32_t)(m * 1024 + (kp & 255) * 2);
        *reinterpret_cast<int4*>(base + swzQ(off))        = *reinterpret_cast<int4*>(hv);
        *reinterpret_cast<int4*>(base + swzQ(off + 512))  = *reinterpret_cast<int4*>(lv);
    }
}

// ---------------- fused persistent kernel ------------------------------------
#define SM_H   0                // 131072 (h: block0 64KB + block1 64KB)
#define SM_W   131072           // 65536 (rec W, swzH 2048B rows)
#define SM_XQ  196608           // 8192
#define SM_P   204800           // 8192
#define SM_C   212992           // 2048
#define SM_TOT 215040

#define GSTAGES 4
#define GA_B 8192
#define GB_B 16384
#define GST_B (GA_B + GB_B)     // 24576; 4 stages = 98304 < SM_TOT

// one 128x256 output tile; data bars (count 1) + free bars (count 256).
__device__ __forceinline__ void gemm_tile(
    uint32_t sbase, uint32_t bar0, uint32_t fbar0, unsigned* ps, unsigned* fs,
    int mt, int nt, int tid, int wid, int lid,
    const float* __restrict__ bq, float* __restrict__ out)
{
    const int m0 = mt * TM, n0 = nt * TN;
    const int wm = (wid >> 2) * 64, wn = (wid & 3) * 64;
    const int lr = lid & 15,  lc = (lid >> 4) * 16;

    auto akc = [](int kt) { return (kt < 32) ? kt : kt - 32; };
    auto bkc = [](int kt) { return (kt < 16) ? kt : kt - 16; };

    float acc[4][8][4];
    #pragma unroll
    for (int i = 0; i < 4; i++)
        #pragma unroll
        for (int jn = 0; jn < 8; jn++)
            #pragma unroll
            for (int q = 0; q < 4; q++) acc[i][jn][q] = 0.0f;

    if (tid == 0) {
        #pragma unroll
        for (int s = 0; s < GSTAGES; s++) {
            uint32_t b = bar0 + s * 8;
            MBARRIER_EXPECT_TX(b, (uint32_t)GST_B);
            bulk_g2s(sbase + s * GST_B,         g_GA + (size_t)(mt * 32 + akc(s)) * GA_B, GA_B, b);
            bulk_g2s(sbase + s * GST_B + GA_B,  g_GB + (size_t)(nt * 32 + bkc(s)) * GB_B, GB_B, b);
        }
    }

    for (int t = 0; t < KTILES; t++) {
        const int s = t % GSTAGES;
        MBARRIER_WAIT_PARITY(bar0 + s * 8, ps[s] & 1u);
        ps[s]++;

        const uint32_t Ab = sbase + s * GST_B;
        const uint32_t Bb = Ab + GA_B;
        uint32_t af[2][4][4], bf[2][4][4];
        #pragma unroll
        for (int ks2 = 0; ks2 < 2; ks2++) {
            #pragma unroll
            for (int i = 0; i < 4; i++)
                ldsm_x4(af[ks2][i], Ab + swzG((uint32_t)((wm + i * 16 + lr) * 64 + ks2 * 32 + lc)));
            #pragma unroll
            for (int jn = 0; jn < 4; jn++)
                ldsm_x4(bf[ks2][jn], Bb + swzG((uint32_t)((wn + jn * 16 + lr) * 64 + ks2 * 32 + lc)));
        }
        MBARRIER_ARRIVE(fbar0 + s * 8);
        unsigned fp = fs[s]++;
        if (t + GSTAGES < KTILES && tid == 0) {
            MBARRIER_WAIT_PARITY(fbar0 + s * 8, fp & 1u);
            int kt = t + GSTAGES;
            uint32_t b = bar0 + s * 8;
            MBARRIER_EXPECT_TX(b, (uint32_t)GST_B);
            bulk_g2s(sbase + s * GST_B,        g_GA + (size_t)(mt * 32 + akc(kt)) * GA_B, GA_B, b);
            bulk_g2s(sbase + s * GST_B + GA_B, g_GB + (size_t)(nt * 32 + bkc(kt)) * GB_B, GB_B, b);
        }
        #pragma unroll
        for (int ks2 = 0; ks2 < 2; ks2++)
            #pragma unroll
            for (int i = 0; i < 4; i++)
                #pragma unroll
                for (int jn = 0; jn < 4; jn++) {
                    mma16816(acc[i][2 * jn],     af[ks2][i], bf[ks2][jn][0], bf[ks2][jn][2]);
                    mma16816(acc[i][2 * jn + 1], af[ks2][i], bf[ks2][jn][1], bf[ks2][jn][3]);
                }
    }

    const int qr = lid >> 2;
    const int qc = (lid & 3) * 2;
    #pragma unroll
    for (int i = 0; i < 4; i++) {
        int mrow = m0 + wm + i * 16 + qr;
        #pragma unroll
        for (int jn = 0; jn < 8; jn++) {
            int n = n0 + wn + jn * 8 + qc;
            if (n < VV) {
                float bx = bq[n], by = bq[n + 1 < VV ? n + 1 : n];
                float2 v0 = {acc[i][jn][0] + bx, acc[i][jn][1] + by};
                float2 v1 = {acc[i][jn][2] + bx, acc[i][jn][3] + by};
                *reinterpret_cast<float2*>(out + (size_t)mrow * VV + n) = v0;
                *reinterpret_cast<float2*>(out + (size_t)(mrow + 8) * VV + n) = v1;
            }
        }
    }
}

__device__ __forceinline__ void gemm_drain(
    uint32_t sbase, uint32_t bar0, uint32_t fbar0, unsigned* ps, unsigned* fs,
    unsigned base, int tid, int wid, int lid, unsigned* s_q,
    const float* __restrict__ bq, float* __restrict__ out)
{
    for (;;) {
        if (tid == 0) *s_q = atomicAdd(&g_tq, 1u);
        __syncthreads();
        unsigned q = *s_q;
        __syncthreads();
        if (q >= QTOTAL) break;
        int mt = (int)(q / NTILES), nt = (int)(q % NTILES);
        if (tid == 0) {
            while ((*(volatile unsigned*)&g_gen) - base < (unsigned)(2 * mt + 3))
                __nanosleep(100);
            __threadfence();
        }
        __syncthreads();
        gemm_tile(sbase, bar0, fbar0, ps, fs, mt, nt, tid, wid, lid, bq, out);
    }
}

__global__ void __launch_bounds__(256, 1)
lstm_fused(const float* __restrict__ cell0, const float* __restrict__ bq,
           float* __restrict__ out) {
    extern __shared__ __align__(128) char sm[];
    __shared__ __align__(8) uint64_t s_hbar[2];
    __shared__ __align__(8) uint64_t s_gbar[GSTAGES];
    __shared__ __align__(8) uint64_t s_gfree[GSTAGES];
    __shared__ unsigned s_base;
    __shared__ unsigned s_q;
    const uint32_t hbase = smem_u32(sm);
    const uint32_t hbar0 = smem_u32(&s_hbar[0]);
    const uint32_t gbar0 = smem_u32(&s_gbar[0]);
    const uint32_t gfree0 = smem_u32(&s_gfree[0]);

    const int tid = threadIdx.x;
    const int wid = tid >> 5;
    const int lid = tid & 31;
    const int cta = blockIdx.x;

    if (tid == 0) {
        MBARRIER_INIT(hbar0, 1);
        MBARRIER_INIT(hbar0 + 8, 1);
        for (int s = 0; s < GSTAGES; s++) {
            MBARRIER_INIT(gbar0 + s * 8, 1);
            MBARRIER_INIT(gfree0 + s * 8, 256);
        }
    }
    __syncthreads();

    // ---- start barrier: capture g_gen base; CTA0 resets queue + step ctr ----
    if (tid == 0) {
        unsigned b = *(volatile unsigned*)&g_gen;
        s_base = b;
        if (cta == 0) {
            atomicExch(&g_tq, 0u);
            atomicExch(&g_cnt, 0u);
        }
        __threadfence();
        unsigned arr = atomicAdd(&g_cnt0, 1u);
        if (arr == ALL_CTAS - 1) {
            atomicExch(&g_cnt0, 0u);
            __threadfence();
            atomicAdd(&g_gen, 1u);
        }
        while ((*(volatile unsigned*)&g_gen) - b < 1u) __nanosleep(40);
    }
    __syncthreads();
    const unsigned base = s_base;
    unsigned ps[GSTAGES] = {0, 0, 0, 0};
    unsigned fs[GSTAGES] = {0, 0, 0, 0};

    if (cta < REC_CTAS) {
        // ================= recurrence (CTAs 0..63) =================
        const uint32_t wbase = hbase + SM_W;
        const uint32_t xqb   = hbase + SM_XQ;
        float* pbuf  = reinterpret_cast<float*>(sm + SM_P);
        float* cellb = reinterpret_cast<float*>(sm + SM_C);
        float* sxq   = reinterpret_cast<float*>(sm + SM_XQ);

        const int j0  = cta * 8;
        const int mg  = wid >> 1;
        const int ng  = wid & 1;
        const int lr  = lid & 15;
        const int lc  = (lid >> 4) * 16;
        // pair-local elementwise role: pair = tid>>6 handles rows [pair*16, +16)
        const int pair = tid >> 6;
        const int erow = pair * 16 + ((tid & 63) >> 2);
        const int u0  = (tid & 3) * 2;
        const int j   = j0 + u0;

        {
            const char* src = g_WB + (size_t)cta * 65536;
            for (int c = tid; c < 4096; c += 256)
                cp_async16(wbase + c * 16, src + (size_t)c * 16);
            asm volatile("cp.async.commit_group;" ::: "memory");
        }
        for (int i = tid; i < 512; i += 256)
            cellb[i] = cell0[(size_t)(i >> 3) * HH + j0 + (i & 7)];
        asm volatile("cp.async.wait_group 0;" ::: "memory");
        __syncthreads();

        const uint32_t rowA = (uint32_t)((mg * 16 + lr) * 1024);
        const uint32_t rowW = (uint32_t)((ng * 16 + lr) * 2048);

        char* const a2wr = g_A2 + (size_t)(j >> 8) * 65536;
        const uint32_t offw_hi = (uint32_t)(erow * 1024 + (j & 255) * 2);

        for (int t = 0; t < TT; t++) {
            if (tid == 0) {
                const char* slot = g_A2 + (size_t)t * 131072;
                MBARRIER_EXPECT_TX(hbar0, 65536u);
                bulk_g2s(hbase, slot, 65536u, hbar0);
                MBARRIER_EXPECT_TX(hbar0 + 8, 65536u + 8192u);
                bulk_g2s(hbase + 65536, slot + 65536, 65536u, hbar0 + 8);
                bulk_g2s(xqb, (const char*)g_XQ + ((size_t)(t * 64 + cta)) * 8192, 8192u, hbar0 + 8);
            }

            float acc0[4] = {0.f, 0.f, 0.f, 0.f};
            float acc1[4] = {0.f, 0.f, 0.f, 0.f};

            // half 0 (k < 256)
            MBARRIER_WAIT_PARITY(hbar0, (uint32_t)(t & 1));
            #pragma unroll 4
            for (int kt = 0; kt < 16; kt++) {
                uint32_t ahi[4], alo[4], bhi[4], blo[4];
                uint32_t ca = rowA + kt * 32 + lc;
                uint32_t cw = rowW + kt * 32 + lc;
                ldsm_x4(ahi, hbase + swzQ(ca));
                ldsm_x4(alo, hbase + swzQ(ca + 512));
                ldsm_x4(bhi, wbase + swzH(cw));
                ldsm_x4(blo, wbase + swzH(cw + 1024));
                mma16816(acc0, ahi, bhi[0], bhi[2]);
                mma16816(acc1, ahi, bhi[1], bhi[3]);
                mma16816(acc0, alo, bhi[0], bhi[2]);
                mma16816(acc1, alo, bhi[1], bhi[3]);
                mma16816(acc0, ahi, blo[0], blo[2]);
                mma16816(acc1, ahi, blo[1], blo[3]);
            }
            // half 1 (k >= 256)
            MBARRIER_WAIT_PARITY(hbar0 + 8, (uint32_t)(t & 1));
            #pragma unroll 4
            for (int kt = 16; kt < 32; kt++) {
                uint32_t ahi[4], alo[4], bhi[4], blo[4];
                uint32_t ca = rowA + (kt - 16) * 32 + lc;
                uint32_t cw = rowW + kt * 32 + lc;
                ldsm_x4(ahi, hbase + 65536 + swzQ(ca));
                ldsm_x4(alo, hbase + 65536 + swzQ(ca + 512));
                ldsm_x4(bhi, wbase + swzH(cw));
                ldsm_x4(blo, wbase + swzH(cw + 1024));
                mma16816(acc0, ahi, bhi[0], bhi[2]);
                mma16816(acc1, ahi, bhi[1], bhi[3]);
                mma16816(acc0, alo, bhi[0], bhi[2]);
                mma16816(acc1, alo, bhi[1], bhi[3]);
                mma16816(acc0, ahi, blo[0], blo[2]);
                mma16816(acc1, ahi, blo[1], blo[3]);
            }

            // fragment -> pbuf (pair mg covers rows [mg*16,+16) x all 32 cols)
            {
                const int qr = lid >> 2;
                const int qc = (lid & 3) * 2;
                int row = mg * 16 + qr;
                int col = ng * 16 + qc;
                pbuf[row * 32 + col]           = acc0[0];
                pbuf[row * 32 + col + 1]       = acc0[1];
                pbuf[(row + 8) * 32 + col]     = acc0[2];
                pbuf[(row + 8) * 32 + col + 1] = acc0[3];
                pbuf[row * 32 + col + 8]       = acc1[0];
                pbuf[row * 32 + col + 9]       = acc1[1];
                pbuf[(row + 8) * 32 + col + 8] = acc1[2];
                pbuf[(row + 8) * 32 + col + 9] = acc1[3];
            }
            // pair-local barrier: warps 2*pair, 2*pair+1 (64 threads)
            BAR_SYNC_PAIR(1 + pair);

            // elementwise (pair-local rows)
            {
                const float* pr = pbuf + erow * 32;
                const float* xr = sxq  + erow * 32;
                float i0 = sigmoidf_(pr[u0]          + xr[u0]);
                float i1 = sigmoidf_(pr[u0 + 1]      + xr[u0 + 1]);
                float f0 = sigmoidf_(pr[8 + u0]      + xr[8 + u0]);
                float f1 = sigmoidf_(pr[8 + u0 + 1]  + xr[8 + u0 + 1]);
                float o0 = sigmoidf_(pr[16 + u0]     + xr[16 + u0]);
                float o1 = sigmoidf_(pr[16 + u0 + 1] + xr[16 + u0 + 1]);
                float g0 = tanhf    (pr[24 + u0]     + xr[24 + u0]);
                float g1 = tanhf    (pr[24 + u0 + 1] + xr[24 + u0 + 1]);

                float c0 = cellb[erow * 8 + u0];
                float c1 = cellb[erow * 8 + u0 + 1];
                float cn0 = fmaf(f0, c0, i0 * g0);
                float cn1 = fmaf(f1, c1, i1 * g1);
                cellb[erow * 8 + u0]     = cn0;
                cellb[erow * 8 + u0 + 1] = cn1;
                float hn0 = o0 * tanhf(cn0);
                float hn1 = o1 * tanhf(cn1);

                __nv_bfloat16 h0 = __float2bfloat16(hn0);
                __nv_bfloat16 h1 = __float2bfloat16(hn1);
                __nv_bfloat16 l0 = __float2bfloat16(hn0 - __bfloat162float(h0));
                __nv_bfloat16 l1 = __float2bfloat16(hn1 - __bfloat162float(h1));
                uint32_t hib = (uint32_t)__bfloat16_as_ushort(h0) |
                               ((uint32_t)__bfloat16_as_ushort(h1) << 16);
                uint32_t lob = (uint32_t)__bfloat16_as_ushort(l0) |
                               ((uint32_t)__bfloat16_as_ushort(l1) << 16);
                char* dst = a2wr + (size_t)(t + 1) * 131072;
                *reinterpret_cast<uint32_t*>(dst + swzQ(offw_hi))        = hib;
                *reinterpret_cast<uint32_t*>(dst + swzQ(offw_hi + 512))  = lob;
                int mt  = t >> 1;
                int row = ((t & 1) << 6) | erow;
                int kcH = j >> 5;
                uint32_t offg = (uint32_t)(row * 64 + ((j & 31) * 2));
                char* ga  = g_GA + (size_t)(mt * 32 + kcH) * GA_B;
                char* gal = g_GA + (size_t)(mt * 32 + 16 + kcH) * GA_B;
                *reinterpret_cast<uint32_t*>(ga  + swzG(offg)) = hib;
                *reinterpret_cast<uint32_t*>(gal + swzG(offg)) = lob;
                if (t == TT - 1) {
                    float2 hv = {hn0, hn1};
                    *reinterpret_cast<float2*>(out + OUT_STATE_OFF + (size_t)erow * HH + j) = hv;
                }
            }
            __syncthreads();
            // rec step barrier: monotonic counter
            if (tid == 0) {
                __threadfence();
                unsigned arr = atomicAdd(&g_cnt, 1u);
                if (arr == (unsigned)((t + 1) * REC_CTAS - 1)) {
                    __threadfence();
                    atomicAdd(&g_gen, 1u);
                } else if (t < TT - 1) {
                    while ((*(volatile unsigned*)&g_gen) - base < (unsigned)(t + 2))
                        __nanosleep(40);
                }
                __threadfence();
            }
            __syncthreads();
        }

        for (int i = tid; i < 512; i += 256)
            out[OUT_CELL_OFF + (size_t)(i >> 3) * HH + j0 + (i & 7)] = cellb[i];
        __syncthreads();

        gemm_drain(hbase, gbar0, gfree0, ps, fs, base, tid, wid, lid, &s_q, bq, out);
    } else {
        gemm_drain(hbase, gbar0, gfree0, ps, fs, base, tid, wid, lid, &s_q, bq, out);
    }
}

// ---------------- launch ----------------
extern "C" void kernel_launch(void* const* d_in, const int* in_sizes, int n_in,
                              void* d_out, int out_size) {
    const int*   x     = (const int*)  d_in[0];
    const float* state = (const float*)d_in[1];
    const float* cell  = (const float*)d_in[2];
    const float* W_xi  = (const float*)d_in[3];
    const float* W_hi  = (const float*)d_in[4];
    const float* b_i   = (const float*)d_in[5];
    const float* W_xf  = (const float*)d_in[6];
    const float* W_hf  = (const float*)d_in[7];
    const float* b_f   = (const float*)d_in[8];
    const float* W_xo  = (const float*)d_in[9];
    const float* W_ho  = (const float*)d_in[10];
    const float* b_o   = (const float*)d_in[11];
    const float* W_xc  = (const float*)d_in[12];
    const float* W_hc  = (const float*)d_in[13];
    const float* b_c   = (const float*)d_in[14];
    const float* W_hq  = (const float*)d_in[15];
    const float* b_q   = (const float*)d_in[16];
    float* out = (float*)d_out;

    cudaFuncSetAttribute(lstm_fused, cudaFuncAttributeMaxDynamicSharedMemorySize, SM_TOT);

    prep1<<<1024 + 32 * NTILES, 256>>>(W_hq, W_hi, W_hf, W_ho, W_hc);
    prep2<<<16384 + 16, 256>>>(x, state, W_xi, W_xf, W_xo, W_xc,
                               b_i, b_f, b_o, b_c);
    lstm_fused<<<ALL_CTAS, 256, SM_TOT>>>(cell, b_q, out);
}